// round 12
// baseline (speedup 1.0000x reference)
#include <cuda_runtime.h>

// out[b, j] = prod_{i<=j} cos(params[i]) * cos(x[b, i])
// (RX/RY product state; CNOT chain => prefix-XOR => prefix product of <Z>.)
//
// R4 structure (best measured): 2 rows/thread, all traffic float4.
// Changes vs R4:
//  - prefix products via in-register Hillis-Steele tree (depth 16 cyc vs 40)
//  - all 20 MUFU.COS independent (throughput-bound, not chained)
//  - 64 blocks x 128 threads (same 8192 threads, fewer blocks to distribute)

#define N_WIRES 10

// In-place inclusive prefix product over a[0..9], log-depth.
__device__ __forceinline__ void prefix10(float* a)
{
#pragma unroll
    for (int d = 1; d < N_WIRES; d <<= 1) {
#pragma unroll
        for (int i = N_WIRES - 1; i >= d; --i)
            a[i] *= a[i - d];
    }
}

__global__ void __launch_bounds__(128)
qgate_kernel(const float4* __restrict__ xv,
             const float* __restrict__ params,
             float4* __restrict__ outv,
             int nPairs)
{
    int t = blockIdx.x * blockDim.x + threadIdx.x;
    if (t >= nPairs) return;

    // Front-batched loads: 5 outstanding LDG.128, one exposed round trip.
    float4 v0 = __ldg(&xv[t * 5 + 0]);
    float4 v1 = __ldg(&xv[t * 5 + 1]);
    float4 v2 = __ldg(&xv[t * 5 + 2]);
    float4 v3 = __ldg(&xv[t * 5 + 3]);
    float4 v4 = __ldg(&xv[t * 5 + 4]);

    // Params prefix (uniform across block; L1-broadcast loads, off crit path).
    float P[N_WIRES];
#pragma unroll
    for (int i = 0; i < N_WIRES; ++i) P[i] = __cosf(params[i]);
    prefix10(P);

    float xs[20] = { v0.x, v0.y, v0.z, v0.w,
                     v1.x, v1.y, v1.z, v1.w,
                     v2.x, v2.y, v2.z, v2.w,
                     v3.x, v3.y, v3.z, v3.w,
                     v4.x, v4.y, v4.z, v4.w };

    float a[N_WIRES], b[N_WIRES];
#pragma unroll
    for (int i = 0; i < N_WIRES; ++i) {
        a[i] = __cosf(xs[i]);               // 20 independent MUFUs
        b[i] = __cosf(xs[N_WIRES + i]);
    }
    prefix10(a);                            // two depth-16 trees, interleavable
    prefix10(b);

    float o[20];
#pragma unroll
    for (int i = 0; i < N_WIRES; ++i) {
        o[i]           = a[i] * P[i];
        o[N_WIRES + i] = b[i] * P[i];
    }

    outv[t * 5 + 0] = make_float4(o[0],  o[1],  o[2],  o[3]);
    outv[t * 5 + 1] = make_float4(o[4],  o[5],  o[6],  o[7]);
    outv[t * 5 + 2] = make_float4(o[8],  o[9],  o[10], o[11]);
    outv[t * 5 + 3] = make_float4(o[12], o[13], o[14], o[15]);
    outv[t * 5 + 4] = make_float4(o[16], o[17], o[18], o[19]);
}

extern "C" void kernel_launch(void* const* d_in, const int* in_sizes, int n_in,
                              void* d_out, int out_size)
{
    const float* x      = (const float*)d_in[0];   // (B, 10) float32
    const float* params = (const float*)d_in[1];   // (10,)  float32
    float* out          = (float*)d_out;           // (B, 10) float32

    int B = in_sizes[0] / N_WIRES;      // 16384 (even)
    int nPairs = B / 2;                 // 8192 threads, 2 rows each
    int threads = 128;
    int blocks = (nPairs + threads - 1) / threads;  // 64
    qgate_kernel<<<blocks, threads>>>((const float4*)x, params,
                                      (float4*)out, nPairs);
}